// round 6
// baseline (speedup 1.0000x reference)
#include <cuda_runtime.h>
#include <cstdint>

#define IN_COLS      8192
#define N_ROWS       8192
#define ROWS_PER_BLK 16
#define BT           256   // block threads = cols per block
#define SLICES_PER_T 4     // supports up to 1024 slices

// Single fused kernel: each block reconstructs the out-col -> in-col map for
// its own 256-column window (block scan of slice lengths + sparse expansion),
// then does the scalar coalesced gather for 16 rows.
__global__ void __launch_bounds__(BT)
fused_gather_kernel(const float* __restrict__ in, float* __restrict__ out,
                    const int* __restrict__ slices_raw, int n_slices, int out_cols) {
    __shared__ int s_idx[BT];
    __shared__ int s_wsum[BT / 32];
    __shared__ int s_is64;

    int t  = threadIdx.x;
    int p0 = blockIdx.x * BT;

    // dtype sniff: int64 LE slices have zero odd 32-bit words.
    if (t == 0) {
        int z = 0;
        for (int k = 0; k < 4 && k < n_slices; k++)
            z |= slices_raw[4 * k + 1] | slices_raw[4 * k + 3];
        s_is64 = (z == 0) ? 1 : 0;
    }
    __syncthreads();
    int is64 = s_is64;

    // Each thread owns SLICES_PER_T consecutive slices.
    int st[SLICES_PER_T], len[SLICES_PER_T];
    int sum = 0;
    #pragma unroll
    for (int k = 0; k < SLICES_PER_T; k++) {
        int i = t * SLICES_PER_T + k;
        int s_ = 0, l = 0;
        if (i < n_slices) {
            if (is64) { s_ = __ldg(&slices_raw[4 * i]); l = __ldg(&slices_raw[4 * i + 2]) - s_; }
            else      { s_ = __ldg(&slices_raw[2 * i]); l = __ldg(&slices_raw[2 * i + 1]) - s_; }
        }
        st[k] = s_; len[k] = l; sum += l;
    }

    // Block-wide exclusive scan of per-thread sums (shfl warp scan + smem).
    int lane = t & 31, wid = t >> 5;
    int v = sum;
    #pragma unroll
    for (int d = 1; d < 32; d <<= 1) {
        int n = __shfl_up_sync(0xFFFFFFFFu, v, d);
        if (lane >= d) v += n;
    }
    if (lane == 31) s_wsum[wid] = v;
    __syncthreads();
    if (wid == 0) {
        int w = (lane < BT / 32) ? s_wsum[lane] : 0;
        #pragma unroll
        for (int d = 1; d < BT / 32; d <<= 1) {
            int n = __shfl_up_sync(0xFFFFFFFFu, w, d);
            if (lane >= d) w += n;
        }
        if (lane < BT / 32) s_wsum[lane] = w;
    }
    __syncthreads();
    int base = ((wid > 0) ? s_wsum[wid - 1] : 0) + (v - sum);  // exclusive prefix

    // Sparse expansion: write entries of my slices that fall in [p0, p0+BT).
    int off = base;
    #pragma unroll
    for (int k = 0; k < SLICES_PER_T; k++) {
        int lo = off     > p0      ? off           : p0;
        int hi = (off + len[k]) < (p0 + BT) ? (off + len[k]) : (p0 + BT);
        for (int j = lo; j < hi; j++)
            s_idx[j - p0] = st[k] + (j - off);
        off += len[k];
    }
    __syncthreads();

    // Gather: one output column per thread, 16 rows.
    int p = p0 + t;
    if (p >= out_cols) return;
    int idx = s_idx[t];
    int r0  = blockIdx.y * ROWS_PER_BLK;

    const float* src = in  + (size_t)r0 * IN_COLS  + idx;
    float*       dst = out + (size_t)r0 * out_cols + p;

    #pragma unroll
    for (int j = 0; j < ROWS_PER_BLK; j++)
        dst[(size_t)j * out_cols] = __ldg(src + (size_t)j * IN_COLS);
}

extern "C" void kernel_launch(void* const* d_in, const int* in_sizes, int n_in,
                              void* d_out, int out_size) {
    const float* input      = (const float*)d_in[0];
    const int*   slices_raw = (const int*)d_in[1];
    float*       out        = (float*)d_out;

    int n_slices = in_sizes[1] / 2;      // 600
    int out_cols = out_size / N_ROWS;    // 12500

    dim3 grid((out_cols + BT - 1) / BT, N_ROWS / ROWS_PER_BLK);
    fused_gather_kernel<<<grid, BT>>>(input, out, slices_raw, n_slices, out_cols);
}

// round 7
// speedup vs baseline: 1.2418x; 1.2418x over previous
#include <cuda_runtime.h>
#include <cstdint>

#define IN_COLS      8192
#define N_ROWS       8192
#define MAX_SLICES   1024
#define MAX_OUT_COLS 16384
#define ROWS_PER_BLK 16
#define GTHREADS     256
#define BTHREADS     1024

// out-col -> in-col map.
__device__ __align__(16) int g_col_idx[MAX_OUT_COLS];

// Parallel build: one block per 256-column output window.
// Shfl-based scan of slice lengths (2 barriers), then 256 threads each
// binary-search their own column's owning slice in smem.
__global__ void __launch_bounds__(BTHREADS)
build_col_idx_kernel(const int* __restrict__ slices_raw, int n_slices, int out_cols) {
    __shared__ int s_cum[MAX_SLICES];    // inclusive prefix of lengths
    __shared__ int s_start[MAX_SLICES];
    __shared__ int s_wsum[BTHREADS / 32];
    __shared__ int s_is64;

    int t = threadIdx.x;

    if (t == 0) {
        // int64 LE: odd 32-bit words are zero high-halves; int32: odd words are ends >= 1.
        int z = 0;
        for (int k = 0; k < 4 && k < n_slices; k++)
            z |= slices_raw[4 * k + 1] | slices_raw[4 * k + 3];
        s_is64 = (z == 0) ? 1 : 0;
    }
    __syncthreads();
    int is64 = s_is64;

    int st = 0, len = 0;
    if (t < n_slices) {
        if (is64) { st = __ldg(&slices_raw[4 * t]); len = __ldg(&slices_raw[4 * t + 2]) - st; }
        else      { st = __ldg(&slices_raw[2 * t]); len = __ldg(&slices_raw[2 * t + 1]) - st; }
    }

    // Two-level shfl scan (inclusive) over BTHREADS entries.
    int lane = t & 31, wid = t >> 5;
    int v = len;
    #pragma unroll
    for (int d = 1; d < 32; d <<= 1) {
        int n = __shfl_up_sync(0xFFFFFFFFu, v, d);
        if (lane >= d) v += n;
    }
    if (lane == 31) s_wsum[wid] = v;
    __syncthreads();
    if (wid == 0) {
        int w = (lane < BTHREADS / 32) ? s_wsum[lane] : 0;
        #pragma unroll
        for (int d = 1; d < BTHREADS / 32; d <<= 1) {
            int n = __shfl_up_sync(0xFFFFFFFFu, w, d);
            if (lane >= d) w += n;
        }
        if (lane < BTHREADS / 32) s_wsum[lane] = w;
    }
    __syncthreads();
    int incl = v + ((wid > 0) ? s_wsum[wid - 1] : 0);

    if (t < n_slices) { s_cum[t] = incl; s_start[t] = st; }
    __syncthreads();

    // First 256 threads: binary-search the owning slice of column p, write map.
    if (t < GTHREADS) {
        int p = blockIdx.x * GTHREADS + t;
        if (p < out_cols) {
            int lo = 0, hi = n_slices - 1;
            while (lo < hi) {                    // first i with s_cum[i] > p
                int mid = (lo + hi) >> 1;
                if (s_cum[mid] > p) hi = mid; else lo = mid + 1;
            }
            int base = (lo == 0) ? 0 : s_cum[lo - 1];
            g_col_idx[p] = s_start[lo] + (p - base);
        }
    }
}

// Scalar gather: one output column per thread (warp-contiguous index stream),
// 16 rows per thread; streaming (evict-first) stores.
__global__ void __launch_bounds__(GTHREADS)
gather_kernel(const float* __restrict__ in, float* __restrict__ out, int out_cols) {
    int p = blockIdx.x * GTHREADS + threadIdx.x;
    if (p >= out_cols) return;

    int idx = g_col_idx[p];
    int r0  = blockIdx.y * ROWS_PER_BLK;

    const float* src = in  + (size_t)r0 * IN_COLS  + idx;
    float*       dst = out + (size_t)r0 * out_cols + p;

    #pragma unroll
    for (int j = 0; j < ROWS_PER_BLK; j++) {
        float v = __ldg(src + (size_t)j * IN_COLS);
        asm volatile("st.global.cs.f32 [%0], %1;"
                     :: "l"(dst + (size_t)j * out_cols), "f"(v) : "memory");
    }
}

extern "C" void kernel_launch(void* const* d_in, const int* in_sizes, int n_in,
                              void* d_out, int out_size) {
    const float* input      = (const float*)d_in[0];
    const int*   slices_raw = (const int*)d_in[1];
    float*       out        = (float*)d_out;

    int n_slices = in_sizes[1] / 2;      // 600
    int out_cols = out_size / N_ROWS;    // 12500

    int nwin = (out_cols + GTHREADS - 1) / GTHREADS;   // 49
    build_col_idx_kernel<<<nwin, BTHREADS>>>(slices_raw, n_slices, out_cols);

    dim3 grid(nwin, N_ROWS / ROWS_PER_BLK);
    gather_kernel<<<grid, GTHREADS>>>(input, out, out_cols);
}

// round 8
// speedup vs baseline: 1.2428x; 1.0008x over previous
#include <cuda_runtime.h>
#include <cstdint>

#define IN_COLS      8192
#define N_ROWS       8192
#define MAX_SLICES   1024
#define MAX_OUT_COLS 16384
#define ROWS_PER_BLK 16
#define GTHREADS     256
#define BTHREADS     1024

// out-col -> in-col map.
__device__ __align__(16) int g_col_idx[MAX_OUT_COLS];

// Parallel build: one block per 256-column output window.
// Shfl-based scan of slice lengths (2 barriers), then 256 threads each
// binary-search their own column's owning slice in smem.
__global__ void __launch_bounds__(BTHREADS)
build_col_idx_kernel(const int* __restrict__ slices_raw, int n_slices, int out_cols) {
    __shared__ int s_cum[MAX_SLICES];    // inclusive prefix of lengths
    __shared__ int s_start[MAX_SLICES];
    __shared__ int s_wsum[BTHREADS / 32];
    __shared__ int s_is64;

    int t = threadIdx.x;

    if (t == 0) {
        // int64 LE: odd 32-bit words are zero high-halves; int32: odd words are ends >= 1.
        int z = 0;
        for (int k = 0; k < 4 && k < n_slices; k++)
            z |= slices_raw[4 * k + 1] | slices_raw[4 * k + 3];
        s_is64 = (z == 0) ? 1 : 0;
    }
    __syncthreads();
    int is64 = s_is64;

    int st = 0, len = 0;
    if (t < n_slices) {
        if (is64) { st = __ldg(&slices_raw[4 * t]); len = __ldg(&slices_raw[4 * t + 2]) - st; }
        else      { st = __ldg(&slices_raw[2 * t]); len = __ldg(&slices_raw[2 * t + 1]) - st; }
    }

    // Two-level shfl scan (inclusive) over BTHREADS entries.
    int lane = t & 31, wid = t >> 5;
    int v = len;
    #pragma unroll
    for (int d = 1; d < 32; d <<= 1) {
        int n = __shfl_up_sync(0xFFFFFFFFu, v, d);
        if (lane >= d) v += n;
    }
    if (lane == 31) s_wsum[wid] = v;
    __syncthreads();
    if (wid == 0) {
        int w = (lane < BTHREADS / 32) ? s_wsum[lane] : 0;
        #pragma unroll
        for (int d = 1; d < BTHREADS / 32; d <<= 1) {
            int n = __shfl_up_sync(0xFFFFFFFFu, w, d);
            if (lane >= d) w += n;
        }
        if (lane < BTHREADS / 32) s_wsum[lane] = w;
    }
    __syncthreads();
    int incl = v + ((wid > 0) ? s_wsum[wid - 1] : 0);

    if (t < n_slices) { s_cum[t] = incl; s_start[t] = st; }
    __syncthreads();

    // First 256 threads: binary-search the owning slice of column p, write map.
    if (t < GTHREADS) {
        int p = blockIdx.x * GTHREADS + t;
        if (p < out_cols) {
            int lo = 0, hi = n_slices - 1;
            while (lo < hi) {                    // first i with s_cum[i] > p
                int mid = (lo + hi) >> 1;
                if (s_cum[mid] > p) hi = mid; else lo = mid + 1;
            }
            int base = (lo == 0) ? 0 : s_cum[lo - 1];
            g_col_idx[p] = s_start[lo] + (p - base);
        }
    }
}

// Scalar gather with PDL: launched concurrently with the build via
// programmatic stream serialization; waits on the build's completion
// only right before consuming g_col_idx.
__global__ void __launch_bounds__(GTHREADS)
gather_kernel(const float* __restrict__ in, float* __restrict__ out, int out_cols) {
    int p = blockIdx.x * GTHREADS + threadIdx.x;
    int r0 = blockIdx.y * ROWS_PER_BLK;

    // Preamble (address math) before the dependency point.
    const float* srcRow = in  + (size_t)r0 * IN_COLS;
    float*       dst    = out + (size_t)r0 * out_cols + p;

    // Wait for the build kernel's writes to g_col_idx to be visible.
    cudaGridDependencySynchronize();

    if (p >= out_cols) return;
    int idx = g_col_idx[p];
    const float* src = srcRow + idx;

    #pragma unroll
    for (int j = 0; j < ROWS_PER_BLK; j++) {
        float v = __ldg(src + (size_t)j * IN_COLS);
        asm volatile("st.global.cs.f32 [%0], %1;"
                     :: "l"(dst + (size_t)j * out_cols), "f"(v) : "memory");
    }
}

extern "C" void kernel_launch(void* const* d_in, const int* in_sizes, int n_in,
                              void* d_out, int out_size) {
    const float* input      = (const float*)d_in[0];
    const int*   slices_raw = (const int*)d_in[1];
    float*       out        = (float*)d_out;

    int n_slices = in_sizes[1] / 2;      // 600
    int out_cols = out_size / N_ROWS;    // 12500

    int nwin = (out_cols + GTHREADS - 1) / GTHREADS;   // 49
    build_col_idx_kernel<<<nwin, BTHREADS>>>(slices_raw, n_slices, out_cols);

    // Gather launched with programmatic dependent launch: overlaps its ramp-up
    // with the build kernel's tail; dependency enforced in-kernel.
    cudaLaunchConfig_t cfg = {};
    cfg.gridDim  = dim3(nwin, N_ROWS / ROWS_PER_BLK, 1);
    cfg.blockDim = dim3(GTHREADS, 1, 1);
    cfg.dynamicSmemBytes = 0;
    cfg.stream = 0;
    cudaLaunchAttribute attr[1];
    attr[0].id = cudaLaunchAttributeProgrammaticStreamSerialization;
    attr[0].val.programmaticStreamSerializationAllowed = 1;
    cfg.attrs = attr;
    cfg.numAttrs = 1;
    cudaLaunchKernelEx(&cfg, gather_kernel, input, out, out_cols);
}

// round 9
// speedup vs baseline: 1.2470x; 1.0034x over previous
#include <cuda_runtime.h>
#include <cstdint>

#define IN_COLS      8192
#define N_ROWS       8192
#define MAX_SLICES   1024
#define MAX_OUT_COLS 16384
#define ROWS_PER_BLK 16
#define GTHREADS     256
#define BTHREADS     1024

// out-col -> in-col map.
__device__ __align__(16) int g_col_idx[MAX_OUT_COLS];

// Parallel build: one block per 256-column output window.
// Fires the PDL trigger immediately so the dependent gather grid can launch
// and run its preamble concurrently; g_col_idx visibility is guaranteed by
// the consumer's cudaGridDependencySynchronize (waits for full completion).
__global__ void __launch_bounds__(BTHREADS)
build_col_idx_kernel(const int* __restrict__ slices_raw, int n_slices, int out_cols) {
    cudaTriggerProgrammaticLaunchCompletion();

    __shared__ int s_cum[MAX_SLICES];    // inclusive prefix of lengths
    __shared__ int s_start[MAX_SLICES];
    __shared__ int s_wsum[BTHREADS / 32];
    __shared__ int s_is64;

    int t = threadIdx.x;

    if (t == 0) {
        // int64 LE: odd 32-bit words are zero high-halves; int32: odd words are ends >= 1.
        int z = 0;
        for (int k = 0; k < 4 && k < n_slices; k++)
            z |= slices_raw[4 * k + 1] | slices_raw[4 * k + 3];
        s_is64 = (z == 0) ? 1 : 0;
    }
    __syncthreads();
    int is64 = s_is64;

    int st = 0, len = 0;
    if (t < n_slices) {
        if (is64) { st = __ldg(&slices_raw[4 * t]); len = __ldg(&slices_raw[4 * t + 2]) - st; }
        else      { st = __ldg(&slices_raw[2 * t]); len = __ldg(&slices_raw[2 * t + 1]) - st; }
    }

    // Two-level shfl scan (inclusive) over BTHREADS entries.
    int lane = t & 31, wid = t >> 5;
    int v = len;
    #pragma unroll
    for (int d = 1; d < 32; d <<= 1) {
        int n = __shfl_up_sync(0xFFFFFFFFu, v, d);
        if (lane >= d) v += n;
    }
    if (lane == 31) s_wsum[wid] = v;
    __syncthreads();
    if (wid == 0) {
        int w = (lane < BTHREADS / 32) ? s_wsum[lane] : 0;
        #pragma unroll
        for (int d = 1; d < BTHREADS / 32; d <<= 1) {
            int n = __shfl_up_sync(0xFFFFFFFFu, w, d);
            if (lane >= d) w += n;
        }
        if (lane < BTHREADS / 32) s_wsum[lane] = w;
    }
    __syncthreads();
    int incl = v + ((wid > 0) ? s_wsum[wid - 1] : 0);

    if (t < n_slices) { s_cum[t] = incl; s_start[t] = st; }
    __syncthreads();

    // First 256 threads: binary-search the owning slice of column p, write map.
    if (t < GTHREADS) {
        int p = blockIdx.x * GTHREADS + t;
        if (p < out_cols) {
            int lo = 0, hi = n_slices - 1;
            while (lo < hi) {                    // first i with s_cum[i] > p
                int mid = (lo + hi) >> 1;
                if (s_cum[mid] > p) hi = mid; else lo = mid + 1;
            }
            int base = (lo == 0) ? 0 : s_cum[lo - 1];
            g_col_idx[p] = s_start[lo] + (p - base);
        }
    }
}

// Scalar gather with PDL: launches while build runs (trigger fired at build
// entry), runs preamble, then parks on the grid dependency before consuming
// g_col_idx.
__global__ void __launch_bounds__(GTHREADS)
gather_kernel(const float* __restrict__ in, float* __restrict__ out, int out_cols) {
    int p  = blockIdx.x * GTHREADS + threadIdx.x;
    int r0 = blockIdx.y * ROWS_PER_BLK;

    // Preamble (address math) before the dependency point.
    const float* srcRow = in  + (size_t)r0 * IN_COLS;
    float*       dst    = out + (size_t)r0 * out_cols + p;

    // Wait for the build kernel to complete (makes g_col_idx visible).
    cudaGridDependencySynchronize();

    if (p >= out_cols) return;
    int idx = g_col_idx[p];
    const float* src = srcRow + idx;

    #pragma unroll
    for (int j = 0; j < ROWS_PER_BLK; j++) {
        float v = __ldg(src + (size_t)j * IN_COLS);
        asm volatile("st.global.cs.f32 [%0], %1;"
                     :: "l"(dst + (size_t)j * out_cols), "f"(v) : "memory");
    }
}

extern "C" void kernel_launch(void* const* d_in, const int* in_sizes, int n_in,
                              void* d_out, int out_size) {
    const float* input      = (const float*)d_in[0];
    const int*   slices_raw = (const int*)d_in[1];
    float*       out        = (float*)d_out;

    int n_slices = in_sizes[1] / 2;      // 600
    int out_cols = out_size / N_ROWS;    // 12500

    int nwin = (out_cols + GTHREADS - 1) / GTHREADS;   // 49
    build_col_idx_kernel<<<nwin, BTHREADS>>>(slices_raw, n_slices, out_cols);

    // Dependent gather: allowed to launch early (build fires the trigger).
    cudaLaunchConfig_t cfg = {};
    cfg.gridDim  = dim3(nwin, N_ROWS / ROWS_PER_BLK, 1);
    cfg.blockDim = dim3(GTHREADS, 1, 1);
    cfg.dynamicSmemBytes = 0;
    cfg.stream = 0;
    cudaLaunchAttribute attr[1];
    attr[0].id = cudaLaunchAttributeProgrammaticStreamSerialization;
    attr[0].val.programmaticStreamSerializationAllowed = 1;
    cfg.attrs = attr;
    cfg.numAttrs = 1;
    cudaLaunchKernelEx(&cfg, gather_kernel, input, out, out_cols);
}